// round 12
// baseline (speedup 1.0000x reference)
#include <cuda_runtime.h>
#include <cuda_fp16.h>
#include <stdint.h>

#define HIDDEN   2048
#define NHEADS   32
#define SEQ      4096
#define NTOK     32768           // B * S
#define MCHUNK   16384           // tokens per pipeline chunk (2 chunks)

// ---------------- scratch (static device globals; no allocation) ----------------
__device__ __half g_x[(size_t)NTOK * HIDDEN];              // LN output fp16     (128 MB)
__device__ __half g_wt[(size_t)4 * HIDDEN * HIDDEN];       // wq^T|wk^T|wv^T|wo^T fp16 (32 MB)
__device__ __half g_qkv[(size_t)NTOK * 3 * HIDDEN];        // q|k|v per token    (402 MB)
__device__ __half g_attn[(size_t)NTOK * HIDDEN];           // attn out fp16      (128 MB)

// ---------------- stream/event infra (created at program init, before harness checkpoints) ----
struct Infra {
    cudaStream_t s2;
    cudaEvent_t eCvt, eQ0, eQ1, eA0, eA1;
    Infra() {
        cudaStreamCreateWithFlags(&s2, cudaStreamNonBlocking);
        cudaEventCreateWithFlags(&eCvt, cudaEventDisableTiming);
        cudaEventCreateWithFlags(&eQ0,  cudaEventDisableTiming);
        cudaEventCreateWithFlags(&eQ1,  cudaEventDisableTiming);
        cudaEventCreateWithFlags(&eA0,  cudaEventDisableTiming);
        cudaEventCreateWithFlags(&eA1,  cudaEventDisableTiming);
    }
};
static Infra g_infra;

// ===================== PTX helpers (baseline sm_80+ features only) =====================
__device__ __forceinline__ uint32_t smem_u32(const void* p) {
    uint32_t a;
    asm("{ .reg .u64 t; cvta.to.shared.u64 t, %1; cvt.u32.u64 %0, t; }" : "=r"(a) : "l"(p));
    return a;
}
#define CP_ASYNC16(dst, src) \
    asm volatile("cp.async.cg.shared.global [%0], [%1], 16;" :: "r"(dst), "l"(src) : "memory")
#define CP_COMMIT() asm volatile("cp.async.commit_group;" ::: "memory")
#define CP_WAIT1()  asm volatile("cp.async.wait_group 1;" ::: "memory")

#define LDSM_X4(r0,r1,r2,r3, addr) \
    asm volatile("ldmatrix.sync.aligned.m8n8.x4.shared.b16 {%0,%1,%2,%3}, [%4];" \
        : "=r"(r0),"=r"(r1),"=r"(r2),"=r"(r3) : "r"(addr))

#define MMA16816(d, a0,a1,a2,a3, b0,b1) \
    asm volatile("mma.sync.aligned.m16n8k16.row.col.f32.f16.f16.f32 " \
        "{%0,%1,%2,%3}, {%4,%5,%6,%7}, {%8,%9}, {%0,%1,%2,%3};" \
        : "+f"((d)[0]),"+f"((d)[1]),"+f"((d)[2]),"+f"((d)[3]) \
        : "r"(a0),"r"(a1),"r"(a2),"r"(a3), "r"(b0),"r"(b1))

#define SWZ(off) ((off) ^ (((off) >> 3) & 0x70))

// ===================== LayerNorm -> fp16 =====================
__device__ __forceinline__ float warp_red(float v) {
    #pragma unroll
    for (int o = 16; o; o >>= 1) v += __shfl_xor_sync(0xffffffffu, v, o);
    return v;
}

__global__ __launch_bounds__(256) void ln_kernel(const float* __restrict__ hs,
                          const float* __restrict__ gamma,
                          const float* __restrict__ beta) {
    int t = blockIdx.x;
    int tid = threadIdx.x;
    const float4* row = (const float4*)(hs + (size_t)t * HIDDEN);
    float4 v0 = row[tid];
    float4 v1 = row[tid + 256];
    float s = v0.x + v0.y + v0.z + v0.w + v1.x + v1.y + v1.z + v1.w;
    float q = v0.x*v0.x + v0.y*v0.y + v0.z*v0.z + v0.w*v0.w
            + v1.x*v1.x + v1.y*v1.y + v1.z*v1.z + v1.w*v1.w;
    s = warp_red(s);
    q = warp_red(q);
    __shared__ float sh_s[8], sh_q[8];
    int w = tid >> 5, l = tid & 31;
    if (l == 0) { sh_s[w] = s; sh_q[w] = q; }
    __syncthreads();
    float st = 0.f, qt = 0.f;
    #pragma unroll
    for (int i = 0; i < 8; i++) { st += sh_s[i]; qt += sh_q[i]; }
    float mean = st * (1.0f / HIDDEN);
    float var  = qt * (1.0f / HIDDEN) - mean * mean;
    float rstd = rsqrtf(var + 1e-5f);

    const float4* g4 = (const float4*)gamma;
    const float4* b4 = (const float4*)beta;
    __half2* out = (__half2*)(g_x + (size_t)t * HIDDEN);
    {
        float4 g = g4[tid], b = b4[tid];
        out[2*tid]   = __floats2half2_rn((v0.x - mean)*rstd*g.x + b.x, (v0.y - mean)*rstd*g.y + b.y);
        out[2*tid+1] = __floats2half2_rn((v0.z - mean)*rstd*g.z + b.z, (v0.w - mean)*rstd*g.w + b.w);
    }
    {
        int i2 = tid + 256;
        float4 g = g4[i2], b = b4[i2];
        out[2*i2]   = __floats2half2_rn((v1.x - mean)*rstd*g.x + b.x, (v1.y - mean)*rstd*g.y + b.y);
        out[2*i2+1] = __floats2half2_rn((v1.z - mean)*rstd*g.z + b.z, (v1.w - mean)*rstd*g.w + b.w);
    }
}

// ===================== weight fp32 -> fp16, transposed (all 4 in one launch) =====================
__global__ __launch_bounds__(256) void cvt_t4_kernel(const float* __restrict__ w0, const float* __restrict__ w1,
                                                     const float* __restrict__ w2, const float* __restrict__ w3,
                                                     __half* __restrict__ obase) {
    const float* w = (blockIdx.z == 0) ? w0 : (blockIdx.z == 1) ? w1 : (blockIdx.z == 2) ? w2 : w3;
    __half* o = obase + (size_t)blockIdx.z * HIDDEN * HIDDEN;
    __shared__ float t[32][33];
    int bx = blockIdx.x * 32;   // n0
    int by = blockIdx.y * 32;   // k0
    int tx = threadIdx.x & 31, ty = threadIdx.x >> 5;
    #pragma unroll
    for (int r = 0; r < 32; r += 8)
        t[ty + r][tx] = w[(size_t)(by + ty + r) * HIDDEN + bx + tx];
    __syncthreads();
    #pragma unroll
    for (int r = 0; r < 32; r += 8)
        o[(size_t)(bx + ty + r) * HIDDEN + by + tx] = __float2half_rn(t[tx][ty + r]);
}

// ===================== pipelined mma.sync GEMM =====================
// C[M,N] = A[M,2048] @ BW^T, BW stored [N,2048] k-contiguous.
// BM=128, BN=128, BK=64. 128 threads = 4 warps (2x2), warp tile 64x64.
// 3-stage cp.async ring (96KB) -> 2 CTAs/SM. Prefetch interleaved into ks-loop.
#define BM 128
#define BN 128
#define BK 64
#define NSTG 3
#define NKT  (HIDDEN / BK)             // 32
#define TILE_A   (BM * 128)            // 16384 B
#define TILE_B   (BN * 128)            // 16384 B
#define STG_BYTES (TILE_A + TILE_B)    // 32768
#define GEMM_SMEM (NSTG * STG_BYTES)   // 98304

// load one quarter (q=0..3) of a stage: A 256 chunks + B 256 chunks of 16B
__device__ __forceinline__ void load_quarter(uint32_t as, uint32_t bs,
                                             const __half* __restrict__ Arow,
                                             const __half* __restrict__ Brow,
                                             int kt, int tid, int q) {
    const __half* a = Arow + kt * BK;
    const __half* b = Brow + kt * BK;
    #pragma unroll
    for (int j = 0; j < 2; j++) {
        int c = q * 256 + tid + j * 128;
        int r = c >> 3, k16 = c & 7;
        uint32_t off = (uint32_t)(r * 128 + k16 * 16);
        CP_ASYNC16(as + SWZ(off), (const char*)(a + (size_t)r * HIDDEN) + k16 * 16);
    }
    #pragma unroll
    for (int j = 0; j < 2; j++) {
        int c = q * 256 + tid + j * 128;
        int r = c >> 3, k16 = c & 7;
        uint32_t off = (uint32_t)(r * 128 + k16 * 16);
        CP_ASYNC16(bs + SWZ(off), (const char*)(b + (size_t)r * HIDDEN) + k16 * 16);
    }
}

template<bool QKV>
__global__ __launch_bounds__(128, 2) void gemm_mma(const __half* __restrict__ A,
                                                   const __half* __restrict__ BW,
                                                   void* __restrict__ Cout) {
    extern __shared__ char smem[];
    uint32_t sb = smem_u32(smem);
    int tid = threadIdx.x;
    int wid = tid >> 5, lane = tid & 31;
    int warp_m = (wid >> 1) * 64;      // 0 or 64
    int warp_n = (wid & 1) * 64;       // 0 or 64
    int m0 = blockIdx.y * BM;
    int n0 = blockIdx.x * BN;

    const __half* Arow = A + (size_t)m0 * HIDDEN;
    const __half* Brow;
    if (QKV) Brow = BW + ((size_t)(n0 >> 11) << 22) + (size_t)(n0 & 2047) * HIDDEN;
    else     Brow = BW + (size_t)n0 * HIDDEN;

    float acc[4][8][4];
    #pragma unroll
    for (int mt = 0; mt < 4; mt++)
        #pragma unroll
        for (int nt = 0; nt < 8; nt++)
            #pragma unroll
            for (int z = 0; z < 4; z++) acc[mt][nt][z] = 0.f;

    // prologue: stages 0,1 <- tiles 0,1
    #pragma unroll
    for (int s = 0; s < NSTG - 1; s++) {
        uint32_t base = sb + s * STG_BYTES;
        #pragma unroll
        for (int q = 0; q < 4; q++)
            load_quarter(base, base + TILE_A, Arow, Brow, s, tid, q);
        CP_COMMIT();
    }

    // per-lane ldmatrix indices (fixed across k)
    int a_row  = warp_m + (lane & 15);             // + mt*16
    int a_kg   = (lane >> 4) * 16;                 // 0 or 16 bytes
    int b_row4 = warp_n + (lane & 7) + ((lane >> 4) << 3);   // + ntp*16
    int b_kg4  = ((lane >> 3) & 1) * 16;

    for (int i = 0; i < NKT; i++) {
        int s = i % NSTG;
        CP_WAIT1();
        __syncthreads();

        int ip = i + NSTG - 1;
        int sn = ip % NSTG;
        uint32_t pbase = sb + sn * STG_BYTES;
        bool do_pf = (ip < NKT);

        uint32_t as_base = sb + s * STG_BYTES;
        uint32_t bs_base = as_base + TILE_A;

        #pragma unroll
        for (int ks = 0; ks < 4; ks++) {
            uint32_t a_frag[4][4];
            uint32_t b_frag[8][2];
            #pragma unroll
            for (int mt = 0; mt < 4; mt++) {
                uint32_t off = (uint32_t)((a_row + mt * 16) * 128 + ks * 32 + a_kg);
                LDSM_X4(a_frag[mt][0], a_frag[mt][1], a_frag[mt][2], a_frag[mt][3],
                        as_base + SWZ(off));
            }
            #pragma unroll
            for (int ntp = 0; ntp < 4; ntp++) {
                uint32_t off = (uint32_t)((b_row4 + ntp * 16) * 128 + ks * 32 + b_kg4);
                LDSM_X4(b_frag[2*ntp][0], b_frag[2*ntp][1],
                        b_frag[2*ntp+1][0], b_frag[2*ntp+1][1],
                        bs_base + SWZ(off));
            }
            if (do_pf) load_quarter(pbase, pbase + TILE_A, Arow, Brow, ip, tid, ks);

            #pragma unroll
            for (int mt = 0; mt < 4; mt++)
                #pragma unroll
                for (int nt = 0; nt < 8; nt++)
                    MMA16816(acc[mt][nt],
                             a_frag[mt][0], a_frag[mt][1], a_frag[mt][2], a_frag[mt][3],
                             b_frag[nt][0], b_frag[nt][1]);
        }
        CP_COMMIT();
    }

    // ---- epilogue: regs -> gmem ----
    int r_base = m0 + warp_m + (lane >> 2);
    int c_base = n0 + warp_n + (lane & 3) * 2;
    #pragma unroll
    for (int mt = 0; mt < 4; mt++) {
        #pragma unroll
        for (int nt = 0; nt < 8; nt++) {
            int row0 = r_base + mt * 16;
            int col  = c_base + nt * 8;
            if (QKV) {
                __half* d0 = (__half*)Cout + (size_t)row0 * (3 * HIDDEN) + col;
                __half* d1 = d0 + (size_t)8 * (3 * HIDDEN);
                *(__half2*)d0 = __floats2half2_rn(acc[mt][nt][0], acc[mt][nt][1]);
                *(__half2*)d1 = __floats2half2_rn(acc[mt][nt][2], acc[mt][nt][3]);
            } else {
                float* d0 = (float*)Cout + (size_t)row0 * HIDDEN + col;
                float* d1 = d0 + (size_t)8 * HIDDEN;
                *(float2*)d0 = make_float2(acc[mt][nt][0], acc[mt][nt][1]);
                *(float2*)d1 = make_float2(acc[mt][nt][2], acc[mt][nt][3]);
            }
        }
    }
}

// ===================== per-token RoPE + 32x32 head-attention =====================
__global__ __launch_bounds__(128) void attn_kernel(int tok0) {
    int t = tok0 + blockIdx.x;
    int s = t & (SEQ - 1);
    int tid = threadIdx.x;

    __shared__ float qs[32][68], ks[32][68], vs[32][68];
    __shared__ float ss[32][33];
    __shared__ float cosv[32], sinv[32];

    if (tid < 32) {
        float e = (float)(2 * tid) / 64.0f;
        float p = powf(10000.0f, e);
        float ang = (float)s * (1.0f / p);
        sinv[tid] = sinf(ang);
        cosv[tid] = cosf(ang);
    }
    __syncthreads();

    const __half* qg = g_qkv + (size_t)t * (3 * HIDDEN);
    const __half* kg = qg + HIDDEN;
    const __half* vg = qg + 2 * HIDDEN;

    #pragma unroll
    for (int idx = tid; idx < HIDDEN; idx += 128) {
        int h = idx >> 6, d = idx & 63;
        float c = cosv[h], sn = sinv[h];
        int p = (d < 32) ? (2 * d + 1) : (2 * (d - 32));
        float sgn = (d < 32) ? -1.0f : 1.0f;
        float qv = __half2float(qg[idx]);
        float qp = __half2float(qg[h * 64 + p]);
        qs[h][d] = qv * c + sgn * qp * sn;
        float kv = __half2float(kg[idx]);
        float kp = __half2float(kg[h * 64 + p]);
        ks[h][d] = kv * c + sgn * kp * sn;
        vs[h][d] = __half2float(vg[idx]);
    }
    __syncthreads();

    {
        int i  = tid >> 2;
        int j0 = (tid & 3) * 8;
        float acc[8] = {0,0,0,0,0,0,0,0};
        #pragma unroll
        for (int d = 0; d < 64; d += 4) {
            float4 q4 = *(const float4*)&qs[i][d];
            #pragma unroll
            for (int jj = 0; jj < 8; jj++) {
                float4 k4 = *(const float4*)&ks[j0 + jj][d];
                acc[jj] += q4.x * k4.x + q4.y * k4.y + q4.z * k4.z + q4.w * k4.w;
            }
        }
        #pragma unroll
        for (int jj = 0; jj < 8; jj++)
            ss[i][j0 + jj] = acc[jj] * 0.125f;
    }
    __syncthreads();

    if (tid < 32) {
        float mx = -1e30f;
        #pragma unroll
        for (int j = 0; j < 32; j++) mx = fmaxf(mx, ss[tid][j]);
        float sum = 0.f;
        #pragma unroll
        for (int j = 0; j < 32; j++) {
            float e = expf(ss[tid][j] - mx);
            ss[tid][j] = e;
            sum += e;
        }
        float inv = 1.0f / sum;
        #pragma unroll
        for (int j = 0; j < 32; j++) ss[tid][j] *= inv;
    }
    __syncthreads();

    {
        int i  = tid >> 2;
        int d0 = (tid & 3) * 16;
        float acc[16];
        #pragma unroll
        for (int z = 0; z < 16; z++) acc[z] = 0.f;
        #pragma unroll
        for (int j = 0; j < 32; j++) {
            float p = ss[i][j];
            #pragma unroll
            for (int dd = 0; dd < 16; dd += 4) {
                float4 v4 = *(const float4*)&vs[j][d0 + dd];
                acc[dd]     += p * v4.x;
                acc[dd + 1] += p * v4.y;
                acc[dd + 2] += p * v4.z;
                acc[dd + 3] += p * v4.w;
            }
        }
        __half* og = g_attn + (size_t)t * HIDDEN + i * 64 + d0;
        #pragma unroll
        for (int dd = 0; dd < 16; dd += 2)
            *(__half2*)(og + dd) = __floats2half2_rn(acc[dd], acc[dd + 1]);
    }
}

// ===================== launch (fork-join pipeline across 2 chunks) =====================
extern "C" void kernel_launch(void* const* d_in, const int* in_sizes, int n_in,
                              void* d_out, int out_size) {
    const float* hs    = (const float*)d_in[0];
    const float* w_q   = (const float*)d_in[1];
    const float* w_k   = (const float*)d_in[2];
    const float* w_v   = (const float*)d_in[3];
    const float* w_o   = (const float*)d_in[4];
    const float* gamma = (const float*)d_in[5];
    const float* beta  = (const float*)d_in[6];

    __half *xdev, *wtdev, *qkvdev, *attndev;
    cudaGetSymbolAddress((void**)&xdev, g_x);
    cudaGetSymbolAddress((void**)&wtdev, g_wt);
    cudaGetSymbolAddress((void**)&qkvdev, g_qkv);
    cudaGetSymbolAddress((void**)&attndev, g_attn);

    cudaFuncSetAttribute(gemm_mma<true>,  cudaFuncAttributeMaxDynamicSharedMemorySize, GEMM_SMEM);
    cudaFuncSetAttribute(gemm_mma<false>, cudaFuncAttributeMaxDynamicSharedMemorySize, GEMM_SMEM);

    cudaStream_t s0 = 0;            // capture-origin (default) stream
    cudaStream_t s2 = g_infra.s2;   // helper stream

    // fork: weight convert on s2, concurrent with LN on s0
    cudaEventRecord(g_infra.eA1, s0);            // reuse as fork marker
    cudaStreamWaitEvent(s2, g_infra.eA1, 0);
    {
        dim3 grid(HIDDEN / 32, HIDDEN / 32, 4);
        cvt_t4_kernel<<<grid, 256, 0, s2>>>(w_q, w_k, w_v, w_o, wtdev);
        cudaEventRecord(g_infra.eCvt, s2);
    }
    ln_kernel<<<NTOK, 256, 0, s0>>>(hs, gamma, beta);
    cudaStreamWaitEvent(s0, g_infra.eCvt, 0);    // qkv needs weights

    // QKV GEMM chunk 0 (tokens 0..MCHUNK)
    {
        dim3 grid(3 * HIDDEN / BN, MCHUNK / BM);   // (48, 128)
        gemm_mma<true><<<grid, 128, GEMM_SMEM, s0>>>(xdev, wtdev, qkvdev);
        cudaEventRecord(g_infra.eQ0, s0);
    }
    // QKV GEMM chunk 1, concurrent with attn chunk 0 on s2
    cudaStreamWaitEvent(s2, g_infra.eQ0, 0);
    attn_kernel<<<MCHUNK, 128, 0, s2>>>(0);
    cudaEventRecord(g_infra.eA0, s2);
    {
        dim3 grid(3 * HIDDEN / BN, MCHUNK / BM);
        gemm_mma<true><<<grid, 128, GEMM_SMEM, s0>>>(xdev + (size_t)MCHUNK * HIDDEN, wtdev,
                                                     qkvdev + (size_t)MCHUNK * 3 * HIDDEN);
        cudaEventRecord(g_infra.eQ1, s0);
    }
    // attn chunk 1 on s2, concurrent with out-GEMM chunk 0 on s0
    cudaStreamWaitEvent(s2, g_infra.eQ1, 0);
    attn_kernel<<<MCHUNK, 128, 0, s2>>>(MCHUNK);
    cudaEventRecord(g_infra.eA1, s2);

    cudaStreamWaitEvent(s0, g_infra.eA0, 0);
    {
        dim3 grid(HIDDEN / BN, MCHUNK / BM);       // (16, 128)
        gemm_mma<false><<<grid, 128, GEMM_SMEM, s0>>>(attndev, wtdev + 3 * (size_t)HIDDEN * HIDDEN, d_out);
    }
    cudaStreamWaitEvent(s0, g_infra.eA1, 0);       // join s2 back before final chunk
    {
        dim3 grid(HIDDEN / BN, MCHUNK / BM);
        gemm_mma<false><<<grid, 128, GEMM_SMEM, s0>>>(attndev + (size_t)MCHUNK * HIDDEN,
                                                      wtdev + 3 * (size_t)HIDDEN * HIDDEN,
                                                      (float*)d_out + (size_t)MCHUNK * HIDDEN);
    }
}

// round 14
// speedup vs baseline: 1.3747x; 1.3747x over previous
#include <cuda_runtime.h>
#include <cuda_fp16.h>
#include <stdint.h>

#define HIDDEN   2048
#define NHEADS   32
#define SEQ      4096
#define NTOK     32768           // B * S

// ---------------- scratch (static device globals; no allocation) ----------------
__device__ __half g_x[(size_t)NTOK * HIDDEN];              // LN output fp16     (128 MB)
__device__ __half g_wt[(size_t)4 * HIDDEN * HIDDEN];       // wq^T|wk^T|wv^T|wo^T fp16 (32 MB)
__device__ __half g_qkv[(size_t)NTOK * 3 * HIDDEN];        // q|k|v per token    (402 MB)
__device__ __half g_attn[(size_t)NTOK * HIDDEN];           // attn out fp16      (128 MB)

// ===================== PTX helpers (baseline sm_80+ features only) =====================
__device__ __forceinline__ uint32_t smem_u32(const void* p) {
    uint32_t a;
    asm("{ .reg .u64 t; cvta.to.shared.u64 t, %1; cvt.u32.u64 %0, t; }" : "=r"(a) : "l"(p));
    return a;
}
#define CP_ASYNC16(dst, src) \
    asm volatile("cp.async.cg.shared.global [%0], [%1], 16;" :: "r"(dst), "l"(src) : "memory")
#define CP_COMMIT() asm volatile("cp.async.commit_group;" ::: "memory")
#define CP_WAIT1()  asm volatile("cp.async.wait_group 1;" ::: "memory")

#define LDSM_X4(r0,r1,r2,r3, addr) \
    asm volatile("ldmatrix.sync.aligned.m8n8.x4.shared.b16 {%0,%1,%2,%3}, [%4];" \
        : "=r"(r0),"=r"(r1),"=r"(r2),"=r"(r3) : "r"(addr))

#define MMA16816(d, a0,a1,a2,a3, b0,b1) \
    asm volatile("mma.sync.aligned.m16n8k16.row.col.f32.f16.f16.f32 " \
        "{%0,%1,%2,%3}, {%4,%5,%6,%7}, {%8,%9}, {%0,%1,%2,%3};" \
        : "+f"((d)[0]),"+f"((d)[1]),"+f"((d)[2]),"+f"((d)[3]) \
        : "r"(a0),"r"(a1),"r"(a2),"r"(a3), "r"(b0),"r"(b1))

#define SWZ(off) ((off) ^ (((off) >> 3) & 0x70))

// ===================== LayerNorm -> fp16 =====================
__device__ __forceinline__ float warp_red(float v) {
    #pragma unroll
    for (int o = 16; o; o >>= 1) v += __shfl_xor_sync(0xffffffffu, v, o);
    return v;
}

__global__ __launch_bounds__(256) void ln_kernel(const float* __restrict__ hs,
                          const float* __restrict__ gamma,
                          const float* __restrict__ beta) {
    int t = blockIdx.x;
    int tid = threadIdx.x;
    const float4* row = (const float4*)(hs + (size_t)t * HIDDEN);
    float4 v0 = row[tid];
    float4 v1 = row[tid + 256];
    float s = v0.x + v0.y + v0.z + v0.w + v1.x + v1.y + v1.z + v1.w;
    float q = v0.x*v0.x + v0.y*v0.y + v0.z*v0.z + v0.w*v0.w
            + v1.x*v1.x + v1.y*v1.y + v1.z*v1.z + v1.w*v1.w;
    s = warp_red(s);
    q = warp_red(q);
    __shared__ float sh_s[8], sh_q[8];
    int w = tid >> 5, l = tid & 31;
    if (l == 0) { sh_s[w] = s; sh_q[w] = q; }
    __syncthreads();
    float st = 0.f, qt = 0.f;
    #pragma unroll
    for (int i = 0; i < 8; i++) { st += sh_s[i]; qt += sh_q[i]; }
    float mean = st * (1.0f / HIDDEN);
    float var  = qt * (1.0f / HIDDEN) - mean * mean;
    float rstd = rsqrtf(var + 1e-5f);

    const float4* g4 = (const float4*)gamma;
    const float4* b4 = (const float4*)beta;
    __half2* out = (__half2*)(g_x + (size_t)t * HIDDEN);
    {
        float4 g = g4[tid], b = b4[tid];
        out[2*tid]   = __floats2half2_rn((v0.x - mean)*rstd*g.x + b.x, (v0.y - mean)*rstd*g.y + b.y);
        out[2*tid+1] = __floats2half2_rn((v0.z - mean)*rstd*g.z + b.z, (v0.w - mean)*rstd*g.w + b.w);
    }
    {
        int i2 = tid + 256;
        float4 g = g4[i2], b = b4[i2];
        out[2*i2]   = __floats2half2_rn((v1.x - mean)*rstd*g.x + b.x, (v1.y - mean)*rstd*g.y + b.y);
        out[2*i2+1] = __floats2half2_rn((v1.z - mean)*rstd*g.z + b.z, (v1.w - mean)*rstd*g.w + b.w);
    }
}

// ===================== weight fp32 -> fp16, transposed (2 matrices per launch) =====================
__global__ __launch_bounds__(256) void cvt_t2_kernel(const float* __restrict__ wa, __half* __restrict__ oa,
                                                     const float* __restrict__ wb, __half* __restrict__ ob) {
    const float* w = (blockIdx.z == 0) ? wa : wb;
    __half*      o = (blockIdx.z == 0) ? oa : ob;
    __shared__ float t[32][33];
    int bx = blockIdx.x * 32;   // n0
    int by = blockIdx.y * 32;   // k0
    int tx = threadIdx.x & 31, ty = threadIdx.x >> 5;
    #pragma unroll
    for (int r = 0; r < 32; r += 8)
        t[ty + r][tx] = w[(size_t)(by + ty + r) * HIDDEN + bx + tx];
    __syncthreads();
    #pragma unroll
    for (int r = 0; r < 32; r += 8)
        o[(size_t)(bx + ty + r) * HIDDEN + by + tx] = __float2half_rn(t[tx][ty + r]);
}

// ===================== pipelined mma.sync GEMM (unchanged from R11 best) =====================
#define BM 128
#define BN 128
#define BK 64
#define NSTG 3
#define NKT  (HIDDEN / BK)             // 32
#define TILE_A   (BM * 128)            // 16384 B
#define TILE_B   (BN * 128)            // 16384 B
#define STG_BYTES (TILE_A + TILE_B)    // 32768
#define GEMM_SMEM (NSTG * STG_BYTES)   // 98304

__device__ __forceinline__ void load_quarter(uint32_t as, uint32_t bs,
                                             const __half* __restrict__ Arow,
                                             const __half* __restrict__ Brow,
                                             int kt, int tid, int q) {
    const __half* a = Arow + kt * BK;
    const __half* b = Brow + kt * BK;
    #pragma unroll
    for (int j = 0; j < 2; j++) {
        int c = q * 256 + tid + j * 128;
        int r = c >> 3, k16 = c & 7;
        uint32_t off = (uint32_t)(r * 128 + k16 * 16);
        CP_ASYNC16(as + SWZ(off), (const char*)(a + (size_t)r * HIDDEN) + k16 * 16);
    }
    #pragma unroll
    for (int j = 0; j < 2; j++) {
        int c = q * 256 + tid + j * 128;
        int r = c >> 3, k16 = c & 7;
        uint32_t off = (uint32_t)(r * 128 + k16 * 16);
        CP_ASYNC16(bs + SWZ(off), (const char*)(b + (size_t)r * HIDDEN) + k16 * 16);
    }
}

template<bool QKV>
__global__ __launch_bounds__(128, 2) void gemm_mma(const __half* __restrict__ A,
                                                   const __half* __restrict__ BW,
                                                   void* __restrict__ Cout) {
    extern __shared__ char smem[];
    uint32_t sb = smem_u32(smem);
    int tid = threadIdx.x;
    int wid = tid >> 5, lane = tid & 31;
    int warp_m = (wid >> 1) * 64;      // 0 or 64
    int warp_n = (wid & 1) * 64;       // 0 or 64
    int m0 = blockIdx.y * BM;
    int n0 = blockIdx.x * BN;

    const __half* Arow = A + (size_t)m0 * HIDDEN;
    const __half* Brow;
    if (QKV) Brow = BW + ((size_t)(n0 >> 11) << 22) + (size_t)(n0 & 2047) * HIDDEN;
    else     Brow = BW + (size_t)n0 * HIDDEN;

    float acc[4][8][4];
    #pragma unroll
    for (int mt = 0; mt < 4; mt++)
        #pragma unroll
        for (int nt = 0; nt < 8; nt++)
            #pragma unroll
            for (int z = 0; z < 4; z++) acc[mt][nt][z] = 0.f;

    #pragma unroll
    for (int s = 0; s < NSTG - 1; s++) {
        uint32_t base = sb + s * STG_BYTES;
        #pragma unroll
        for (int q = 0; q < 4; q++)
            load_quarter(base, base + TILE_A, Arow, Brow, s, tid, q);
        CP_COMMIT();
    }

    int a_row  = warp_m + (lane & 15);             // + mt*16
    int a_kg   = (lane >> 4) * 16;                 // 0 or 16 bytes
    int b_row4 = warp_n + (lane & 7) + ((lane >> 4) << 3);   // + ntp*16
    int b_kg4  = ((lane >> 3) & 1) * 16;

    for (int i = 0; i < NKT; i++) {
        int s = i % NSTG;
        CP_WAIT1();
        __syncthreads();

        int ip = i + NSTG - 1;
        int sn = ip % NSTG;
        uint32_t pbase = sb + sn * STG_BYTES;
        bool do_pf = (ip < NKT);

        uint32_t as_base = sb + s * STG_BYTES;
        uint32_t bs_base = as_base + TILE_A;

        #pragma unroll
        for (int ks = 0; ks < 4; ks++) {
            uint32_t a_frag[4][4];
            uint32_t b_frag[8][2];
            #pragma unroll
            for (int mt = 0; mt < 4; mt++) {
                uint32_t off = (uint32_t)((a_row + mt * 16) * 128 + ks * 32 + a_kg);
                LDSM_X4(a_frag[mt][0], a_frag[mt][1], a_frag[mt][2], a_frag[mt][3],
                        as_base + SWZ(off));
            }
            #pragma unroll
            for (int ntp = 0; ntp < 4; ntp++) {
                uint32_t off = (uint32_t)((b_row4 + ntp * 16) * 128 + ks * 32 + b_kg4);
                LDSM_X4(b_frag[2*ntp][0], b_frag[2*ntp][1],
                        b_frag[2*ntp+1][0], b_frag[2*ntp+1][1],
                        bs_base + SWZ(off));
            }
            if (do_pf) load_quarter(pbase, pbase + TILE_A, Arow, Brow, ip, tid, ks);

            #pragma unroll
            for (int mt = 0; mt < 4; mt++)
                #pragma unroll
                for (int nt = 0; nt < 8; nt++)
                    MMA16816(acc[mt][nt],
                             a_frag[mt][0], a_frag[mt][1], a_frag[mt][2], a_frag[mt][3],
                             b_frag[nt][0], b_frag[nt][1]);
        }
        CP_COMMIT();
    }

    int r_base = m0 + warp_m + (lane >> 2);
    int c_base = n0 + warp_n + (lane & 3) * 2;
    #pragma unroll
    for (int mt = 0; mt < 4; mt++) {
        #pragma unroll
        for (int nt = 0; nt < 8; nt++) {
            int row0 = r_base + mt * 16;
            int col  = c_base + nt * 8;
            if (QKV) {
                __half* d0 = (__half*)Cout + (size_t)row0 * (3 * HIDDEN) + col;
                __half* d1 = d0 + (size_t)8 * (3 * HIDDEN);
                *(__half2*)d0 = __floats2half2_rn(acc[mt][nt][0], acc[mt][nt][1]);
                *(__half2*)d1 = __floats2half2_rn(acc[mt][nt][2], acc[mt][nt][3]);
            } else {
                float* d0 = (float*)Cout + (size_t)row0 * HIDDEN + col;
                float* d1 = d0 + (size_t)8 * HIDDEN;
                *(float2*)d0 = make_float2(acc[mt][nt][0], acc[mt][nt][1]);
                *(float2*)d1 = make_float2(acc[mt][nt][2], acc[mt][nt][3]);
            }
        }
    }
}

// ===================== per-token RoPE + 32x32 head-attention (fp16 smem, conflict-free) =====================
// smem rows: 33 half2 (66 halfs) per head -> bank(j,d2) = (33j + d2) % 32 = (j + d2) % 32.
// Score phase reads K rows {j0, j0+8, j0+16, j0+24}: banks 8 apart -> conflict-free.
#define AROW 33   // half2 per row

__global__ __launch_bounds__(128) void attn_kernel() {
    int t = blockIdx.x;
    int s = t & (SEQ - 1);
    int tid = threadIdx.x;

    __shared__ __half2 qs[32 * AROW], ks[32 * AROW], vs[32 * AROW];
    __shared__ float ss[32][33];
    __shared__ float cosv[32], sinv[32];

    if (tid < 32) {
        float e = (float)(2 * tid) / 64.0f;
        float p = powf(10000.0f, e);
        float ang = (float)s * (1.0f / p);
        sinv[tid] = sinf(ang);
        cosv[tid] = cosf(ang);
    }
    __syncthreads();

    const __half* qg = g_qkv + (size_t)t * (3 * HIDDEN);
    const __half* kg = qg + HIDDEN;
    const __half* vg = qg + 2 * HIDDEN;

    // RoPE: each of 128 threads handles 16 (h,d2) half2 pairs (d = 2*d2, 2*d2+1)
    #pragma unroll
    for (int it = 0; it < 8; it++) {
        int idx2 = tid + it * 128;           // 0..1023 half2 index
        int h = idx2 >> 5, d2 = idx2 & 31;
        float c = cosv[h], sn = sinv[h];
        int d0 = 2 * d2, d1 = d0 + 1;
        // partner index & sign for rotate_half: d<32 -> p=2d+1, sgn=-1 ; d>=32 -> p=2(d-32), sgn=+1
        int p0 = (d0 < 32) ? (2 * d0 + 1) : (2 * (d0 - 32));
        float sg0 = (d0 < 32) ? -1.0f : 1.0f;
        int p1 = (d1 < 32) ? (2 * d1 + 1) : (2 * (d1 - 32));
        float sg1 = (d1 < 32) ? -1.0f : 1.0f;
        int base = h * 64;

        float q0 = __half2float(qg[base + d0]), q0p = __half2float(qg[base + p0]);
        float q1 = __half2float(qg[base + d1]), q1p = __half2float(qg[base + p1]);
        qs[h * AROW + d2] = __floats2half2_rn(q0 * c + sg0 * q0p * sn, q1 * c + sg1 * q1p * sn);

        float k0 = __half2float(kg[base + d0]), k0p = __half2float(kg[base + p0]);
        float k1 = __half2float(kg[base + d1]), k1p = __half2float(kg[base + p1]);
        ks[h * AROW + d2] = __floats2half2_rn(k0 * c + sg0 * k0p * sn, k1 * c + sg1 * k1p * sn);

        vs[h * AROW + d2] = *(const __half2*)(vg + base + d0);
    }
    __syncthreads();

    // scores: thread (i = tid>>2, j0 = (tid&3)*8) computes 8 columns
    {
        int i  = tid >> 2;
        int j0 = (tid & 3) * 8;
        const __half2* qrow = qs + i * AROW;
        float acc[8] = {0,0,0,0,0,0,0,0};
        #pragma unroll
        for (int d2 = 0; d2 < 32; d2++) {
            float2 qf = __half22float2(qrow[d2]);
            #pragma unroll
            for (int jj = 0; jj < 8; jj++) {
                float2 kf = __half22float2(ks[(j0 + jj) * AROW + d2]);
                acc[jj] += qf.x * kf.x + qf.y * kf.y;
            }
        }
        #pragma unroll
        for (int jj = 0; jj < 8; jj++)
            ss[i][j0 + jj] = acc[jj] * 0.125f;   // 1/sqrt(64)
    }
    __syncthreads();

    // softmax per row (threads 0..31)
    if (tid < 32) {
        float mx = -1e30f;
        #pragma unroll
        for (int j = 0; j < 32; j++) mx = fmaxf(mx, ss[tid][j]);
        float sum = 0.f;
        #pragma unroll
        for (int j = 0; j < 32; j++) {
            float e = expf(ss[tid][j] - mx);
            ss[tid][j] = e;
            sum += e;
        }
        float inv = 1.0f / sum;
        #pragma unroll
        for (int j = 0; j < 32; j++) ss[tid][j] *= inv;
    }
    __syncthreads();

    // out[i, d0..d0+15] = sum_j probs[i][j] * v[j][d]   (d2 block of 8 half2)
    {
        int i   = tid >> 2;
        int dd0 = (tid & 3) * 8;                 // half2 offset within row
        float2 acc[8];
        #pragma unroll
        for (int z = 0; z < 8; z++) acc[z] = make_float2(0.f, 0.f);
        #pragma unroll
        for (int j = 0; j < 32; j++) {
            float p = ss[i][j];
            const __half2* vrow = vs + j * AROW + dd0;
            #pragma unroll
            for (int z = 0; z < 8; z++) {
                float2 vf = __half22float2(vrow[z]);
                acc[z].x += p * vf.x;
                acc[z].y += p * vf.y;
            }
        }
        __half* og = g_attn + (size_t)t * HIDDEN + i * 64 + dd0 * 2;
        #pragma unroll
        for (int z = 0; z < 8; z += 4) {
            __align__(16) __half2 o[4];
            o[0] = __floats2half2_rn(acc[z+0].x, acc[z+0].y);
            o[1] = __floats2half2_rn(acc[z+1].x, acc[z+1].y);
            o[2] = __floats2half2_rn(acc[z+2].x, acc[z+2].y);
            o[3] = __floats2half2_rn(acc[z+3].x, acc[z+3].y);
            *(uint4*)(og + z * 2) = *(const uint4*)o;
        }
    }
}

// ===================== launch (serial, 6 launches) =====================
extern "C" void kernel_launch(void* const* d_in, const int* in_sizes, int n_in,
                              void* d_out, int out_size) {
    const float* hs    = (const float*)d_in[0];
    const float* w_q   = (const float*)d_in[1];
    const float* w_k   = (const float*)d_in[2];
    const float* w_v   = (const float*)d_in[3];
    const float* w_o   = (const float*)d_in[4];
    const float* gamma = (const float*)d_in[5];
    const float* beta  = (const float*)d_in[6];

    __half *xdev, *wtdev, *qkvdev, *attndev;
    cudaGetSymbolAddress((void**)&xdev, g_x);
    cudaGetSymbolAddress((void**)&wtdev, g_wt);
    cudaGetSymbolAddress((void**)&qkvdev, g_qkv);
    cudaGetSymbolAddress((void**)&attndev, g_attn);

    cudaFuncSetAttribute(gemm_mma<true>,  cudaFuncAttributeMaxDynamicSharedMemorySize, GEMM_SMEM);
    cudaFuncSetAttribute(gemm_mma<false>, cudaFuncAttributeMaxDynamicSharedMemorySize, GEMM_SMEM);

    // 1) LayerNorm -> fp16            (launch 0)
    ln_kernel<<<NTOK, 256>>>(hs, gamma, beta);

    // 2) weights: fp32 -> fp16 transposed, 2 matrices per launch (launches 1,2)
    {
        dim3 grid(HIDDEN / 32, HIDDEN / 32, 2);
        cvt_t2_kernel<<<grid, 256>>>(w_q, wtdev + 0 * (size_t)HIDDEN * HIDDEN,
                                     w_k, wtdev + 1 * (size_t)HIDDEN * HIDDEN);
        cvt_t2_kernel<<<grid, 256>>>(w_v, wtdev + 2 * (size_t)HIDDEN * HIDDEN,
                                     w_o, wtdev + 3 * (size_t)HIDDEN * HIDDEN);
    }

    // 3) QKV GEMM: [32768, 6144] fp16 (launch 3)
    {
        dim3 grid(3 * HIDDEN / BN, NTOK / BM);   // (48, 256)
        gemm_mma<true><<<grid, 128, GEMM_SMEM>>>(xdev, wtdev, qkvdev);
    }

    // 4) RoPE + per-token head attention (launch 4)
    attn_kernel<<<NTOK, 128>>>();

    // 5) Output GEMM: [32768, 2048] fp32 -> d_out (launch 5)
    {
        dim3 grid(HIDDEN / BN, NTOK / BM);       // (16, 256)
        gemm_mma<false><<<grid, 128, GEMM_SMEM>>>(attndev, wtdev + 3 * (size_t)HIDDEN * HIDDEN, d_out);
    }
}